// round 3
// baseline (speedup 1.0000x reference)
#include <cuda_runtime.h>
#include <cuda_bf16.h>
#include <cstdint>

#define N_NODES 50000
#define N_EDGES 625000
#define C 128

// Scratch (no allocations allowed -> __device__ globals; sanctioned per pitfalls.md)
__device__ float g_y[(size_t)N_NODES * C];   // x @ W^T
__device__ float g_dis[N_NODES];             // deg, then deg^-1/2 in place
__device__ float g_Wt[C * C];                // W transposed: g_Wt[i*C+o] = W[o*C+i]
__device__ int   g_row[N_EDGES];
__device__ int   g_col[N_EDGES];
__device__ int   g_is64;                     // 1 if edge_index stored as int64

// ---------------------------------------------------------------------------
// Detect edge_index dtype. int64-true data: all sampled values in [0,N_NODES).
// int32-true data read as int64: hi word = next index, ~always nonzero -> OOR.
__global__ void k_detect(const long long* __restrict__ ei) {
    __shared__ int ok;
    if (threadIdx.x == 0) ok = 1;
    __syncthreads();
    for (int i = threadIdx.x; i < 1024; i += blockDim.x) {
        long long v = ei[i];
        if (v < 0 || v >= N_NODES) atomicExch(&ok, 0);
    }
    __syncthreads();
    if (threadIdx.x == 0) g_is64 = ok;
}

// Normalize edges into int arrays regardless of on-device dtype.
__global__ void k_norm_edges(const void* __restrict__ ei) {
    int e = blockIdx.x * blockDim.x + threadIdx.x;
    if (e >= N_EDGES) return;
    if (g_is64) {
        const long long* p = (const long long*)ei;
        g_row[e] = (int)p[e];
        g_col[e] = (int)p[e + N_EDGES];
    } else {
        const int* p = (const int*)ei;
        g_row[e] = p[e];
        g_col[e] = p[e + N_EDGES];
    }
}

// ---------------------------------------------------------------------------
__global__ void k_zero_deg() {
    int i = blockIdx.x * blockDim.x + threadIdx.x;
    if (i < N_NODES) g_dis[i] = 0.f;
}

__global__ void k_count_deg() {
    int e = blockIdx.x * blockDim.x + threadIdx.x;
    if (e < N_EDGES) {
        unsigned r = (unsigned)g_row[e];
        if (r < N_NODES) atomicAdd(&g_dis[r], 1.f);
    }
}

__global__ void k_finalize_dis() {
    int i = blockIdx.x * blockDim.x + threadIdx.x;
    if (i < N_NODES) {
        float d = g_dis[i];
        g_dis[i] = (d > 0.f) ? rsqrtf(d) : 0.f;
    }
}

// ---------------------------------------------------------------------------
__global__ void k_transpose_w(const float* __restrict__ W) {
    int idx = blockIdx.x * blockDim.x + threadIdx.x;  // 16384 elements
    if (idx < C * C) {
        int o = idx >> 7;       // row of W
        int i = idx & 127;      // col of W
        g_Wt[i * C + o] = W[idx];
    }
}

// ---------------------------------------------------------------------------
// y = x @ W^T using pre-transposed Wt (Wt[k][o]); W^T (64KB) stays L1-resident.
// Block: 128 threads = 32 col-groups (4 output cols each) x 4 row-groups.
// 32 rows of x per block staged in 16KB static smem.
#define GROWS 32

__global__ void __launch_bounds__(128) k_gemm(const float* __restrict__ x) {
    __shared__ float xs[GROWS * C];       // 16KB

    const int tid = threadIdx.x;          // 0..127
    const int row0 = blockIdx.x * GROWS;
    const int nrows = min(GROWS, N_NODES - row0);

    // Load x rows (zero-pad tail rows so compute loop needs no guards)
    for (int idx = tid; idx < GROWS * 32; idx += 128) {
        int r = idx >> 5, q = idx & 31;
        float4 v = make_float4(0.f, 0.f, 0.f, 0.f);
        if (r < nrows)
            v = ((const float4*)(x + (size_t)(row0 + r) * C))[q];
        ((float4*)(xs + r * C))[q] = v;
    }
    __syncthreads();

    const int cg = tid & 31;   // output column group: cols 4cg..4cg+3
    const int rg = tid >> 5;   // row group 0..3 (rows rg, rg+4, ...)

    float acc[8][4];
#pragma unroll
    for (int i = 0; i < 8; i++)
#pragma unroll
        for (int j = 0; j < 4; j++) acc[i][j] = 0.f;

    const float* wb = g_Wt + 4 * cg;
#pragma unroll 4
    for (int k = 0; k < C; k += 4) {
        const float4 w0 = __ldg((const float4*)(wb + (size_t)(k + 0) * C));
        const float4 w1 = __ldg((const float4*)(wb + (size_t)(k + 1) * C));
        const float4 w2 = __ldg((const float4*)(wb + (size_t)(k + 2) * C));
        const float4 w3 = __ldg((const float4*)(wb + (size_t)(k + 3) * C));
#pragma unroll
        for (int r8 = 0; r8 < 8; r8++) {
            const float4 xv = *(const float4*)(xs + (rg + 4 * r8) * C + k);
            acc[r8][0] += xv.x * w0.x + xv.y * w1.x + xv.z * w2.x + xv.w * w3.x;
            acc[r8][1] += xv.x * w0.y + xv.y * w1.y + xv.z * w2.y + xv.w * w3.y;
            acc[r8][2] += xv.x * w0.z + xv.y * w1.z + xv.z * w2.z + xv.w * w3.z;
            acc[r8][3] += xv.x * w0.w + xv.y * w1.w + xv.z * w2.w + xv.w * w3.w;
        }
    }

#pragma unroll
    for (int r8 = 0; r8 < 8; r8++) {
        int r = rg + 4 * r8;
        if (r < nrows) {
            *(float4*)(g_y + (size_t)(row0 + r) * C + 4 * cg) =
                make_float4(acc[r8][0], acc[r8][1], acc[r8][2], acc[r8][3]);
        }
    }
}

// ---------------------------------------------------------------------------
// out[i][j] = b[j]  (bias init; scatter accumulates on top)
__global__ void k_init_out(float* __restrict__ out, const float* __restrict__ b) {
    int i = blockIdx.x * blockDim.x + threadIdx.x;  // float4 index
    if (i < N_NODES * (C / 4)) {
        ((float4*)out)[i] = ((const float4*)b)[i & 31];
    }
}

// ---------------------------------------------------------------------------
// Warp per edge: out[row] += norm * y[col]
__global__ void k_scatter(float* __restrict__ out) {
    int gtid = blockIdx.x * blockDim.x + threadIdx.x;
    int e = gtid >> 5;
    int lane = gtid & 31;
    if (e >= N_EDGES) return;
    unsigned r = (unsigned)g_row[e];
    unsigned c = (unsigned)g_col[e];
    if (r >= N_NODES || c >= N_NODES) return;
    float norm = g_dis[r] * g_dis[c];
    if (norm == 0.f) return;
    float4 v = ((const float4*)(g_y + (size_t)c * C))[lane];
    float* dst = out + (size_t)r * C + lane * 4;
    atomicAdd(dst + 0, norm * v.x);
    atomicAdd(dst + 1, norm * v.y);
    atomicAdd(dst + 2, norm * v.z);
    atomicAdd(dst + 3, norm * v.w);
}

// ---------------------------------------------------------------------------
extern "C" void kernel_launch(void* const* d_in, const int* in_sizes, int n_in,
                              void* d_out, int out_size) {
    const float* x = (const float*)d_in[0];               // [50000,128] f32
    const void*  ei = d_in[1];                            // [2,625000] int (32 or 64)
    const float* W = (const float*)d_in[2];               // [128,128] f32
    const float* b = (const float*)d_in[3];               // [128] f32
    float* out = (float*)d_out;                           // [50000,128] f32

    k_detect<<<1, 256>>>((const long long*)ei);
    k_norm_edges<<<(N_EDGES + 255) / 256, 256>>>(ei);

    k_zero_deg<<<(N_NODES + 255) / 256, 256>>>();
    k_count_deg<<<(N_EDGES + 255) / 256, 256>>>();
    k_finalize_dis<<<(N_NODES + 255) / 256, 256>>>();

    k_transpose_w<<<(C * C + 255) / 256, 256>>>(W);
    k_gemm<<<(N_NODES + GROWS - 1) / GROWS, 128>>>(x);

    k_init_out<<<(N_NODES * (C / 4) + 255) / 256, 256>>>(out, b);

    const int threads = 256;
    const long long total = (long long)N_EDGES * 32;
    k_scatter<<<(int)((total + threads - 1) / threads), threads>>>(out);
}

// round 4
// speedup vs baseline: 1.6250x; 1.6250x over previous
#include <cuda_runtime.h>
#include <cuda_bf16.h>
#include <cstdint>

#define N_NODES 50000
#define N_EDGES 625000
#define C 128
#define SCAN_T 1024
#define SCAN_CH ((N_NODES + SCAN_T - 1) / SCAN_T)   // 49

// Scratch (__device__ globals; allocations are banned)
__device__ float g_y[(size_t)N_NODES * C];   // x @ W^T
__device__ float g_dis[N_NODES];             // deg^-1/2
__device__ float g_Wt[C * C];                // W transposed
__device__ int   g_row[N_EDGES];
__device__ int   g_col[N_EDGES];
__device__ int   g_cnt[N_NODES];             // degree counts
__device__ int   g_cur[N_NODES];             // fill cursors
__device__ int   g_off[N_NODES + 1];         // CSR offsets
__device__ int   g_ecol[N_EDGES];            // CSR column (src) ids
__device__ int   g_is64;

// ---------------------------------------------------------------------------
__global__ void k_detect(const long long* __restrict__ ei) {
    __shared__ int ok;
    if (threadIdx.x == 0) ok = 1;
    __syncthreads();
    for (int i = threadIdx.x; i < 1024; i += blockDim.x) {
        long long v = ei[i];
        if (v < 0 || v >= N_NODES) atomicExch(&ok, 0);
    }
    __syncthreads();
    if (threadIdx.x == 0) g_is64 = ok;
}

__global__ void k_norm_edges(const void* __restrict__ ei) {
    int e = blockIdx.x * blockDim.x + threadIdx.x;
    if (e >= N_EDGES) return;
    int r, c;
    if (g_is64) {
        const long long* p = (const long long*)ei;
        r = (int)p[e];
        c = (int)p[e + N_EDGES];
    } else {
        const int* p = (const int*)ei;
        r = p[e];
        c = p[e + N_EDGES];
    }
    g_row[e] = r;
    g_col[e] = c;
}

// ---------------------------------------------------------------------------
__global__ void k_zero() {
    int i = blockIdx.x * blockDim.x + threadIdx.x;
    if (i < N_NODES) { g_cnt[i] = 0; g_cur[i] = 0; }
}

__global__ void k_count_deg() {
    int e = blockIdx.x * blockDim.x + threadIdx.x;
    if (e < N_EDGES) {
        unsigned r = (unsigned)g_row[e];
        if (r < N_NODES) atomicAdd(&g_cnt[r], 1);
    }
}

__global__ void k_finalize_dis() {
    int i = blockIdx.x * blockDim.x + threadIdx.x;
    if (i < N_NODES) {
        int d = g_cnt[i];
        g_dis[i] = (d > 0) ? rsqrtf((float)d) : 0.f;
    }
}

// Single-block exclusive scan over g_cnt -> g_off
__global__ void __launch_bounds__(SCAN_T) k_scan() {
    __shared__ int part[SCAN_T];
    const int t = threadIdx.x;
    const int base = t * SCAN_CH;
    int s = 0;
    for (int i = base; i < base + SCAN_CH && i < N_NODES; i++) s += g_cnt[i];
    part[t] = s;
    __syncthreads();
    // Hillis-Steele inclusive scan
    for (int off = 1; off < SCAN_T; off <<= 1) {
        int v = (t >= off) ? part[t - off] : 0;
        __syncthreads();
        part[t] += v;
        __syncthreads();
    }
    int run = (t == 0) ? 0 : part[t - 1];
    for (int i = base; i < base + SCAN_CH && i < N_NODES; i++) {
        g_off[i] = run;
        run += g_cnt[i];
    }
    if (t == SCAN_T - 1) g_off[N_NODES] = run;
}

__global__ void k_fill_csr() {
    int e = blockIdx.x * blockDim.x + threadIdx.x;
    if (e >= N_EDGES) return;
    unsigned r = (unsigned)g_row[e];
    unsigned c = (unsigned)g_col[e];
    if (r >= N_NODES || c >= N_NODES) return;
    int pos = g_off[r] + atomicAdd(&g_cur[r], 1);
    g_ecol[pos] = (int)c;
}

// ---------------------------------------------------------------------------
__global__ void k_transpose_w(const float* __restrict__ W) {
    int idx = blockIdx.x * blockDim.x + threadIdx.x;
    if (idx < C * C) {
        int o = idx >> 7, i = idx & 127;
        g_Wt[i * C + o] = W[idx];
    }
}

// ---------------------------------------------------------------------------
// y = x @ W^T ; W^T (64KB) L1-resident. 32 rows/block, 128 threads.
#define GROWS 32

__global__ void __launch_bounds__(128) k_gemm(const float* __restrict__ x) {
    __shared__ float xs[GROWS * C];

    const int tid = threadIdx.x;
    const int row0 = blockIdx.x * GROWS;
    const int nrows = min(GROWS, N_NODES - row0);

    for (int idx = tid; idx < GROWS * 32; idx += 128) {
        int r = idx >> 5, q = idx & 31;
        float4 v = make_float4(0.f, 0.f, 0.f, 0.f);
        if (r < nrows)
            v = ((const float4*)(x + (size_t)(row0 + r) * C))[q];
        ((float4*)(xs + r * C))[q] = v;
    }
    __syncthreads();

    const int cg = tid & 31;
    const int rg = tid >> 5;

    float acc[8][4];
#pragma unroll
    for (int i = 0; i < 8; i++)
#pragma unroll
        for (int j = 0; j < 4; j++) acc[i][j] = 0.f;

    const float* wb = g_Wt + 4 * cg;
#pragma unroll 4
    for (int k = 0; k < C; k += 4) {
        const float4 w0 = __ldg((const float4*)(wb + (size_t)(k + 0) * C));
        const float4 w1 = __ldg((const float4*)(wb + (size_t)(k + 1) * C));
        const float4 w2 = __ldg((const float4*)(wb + (size_t)(k + 2) * C));
        const float4 w3 = __ldg((const float4*)(wb + (size_t)(k + 3) * C));
#pragma unroll
        for (int r8 = 0; r8 < 8; r8++) {
            const float4 xv = *(const float4*)(xs + (rg + 4 * r8) * C + k);
            acc[r8][0] += xv.x * w0.x + xv.y * w1.x + xv.z * w2.x + xv.w * w3.x;
            acc[r8][1] += xv.x * w0.y + xv.y * w1.y + xv.z * w2.y + xv.w * w3.y;
            acc[r8][2] += xv.x * w0.z + xv.y * w1.z + xv.z * w2.z + xv.w * w3.z;
            acc[r8][3] += xv.x * w0.w + xv.y * w1.w + xv.z * w2.w + xv.w * w3.w;
        }
    }

#pragma unroll
    for (int r8 = 0; r8 < 8; r8++) {
        int r = rg + 4 * r8;
        if (r < nrows) {
            *(float4*)(g_y + (size_t)(row0 + r) * C + 4 * cg) =
                make_float4(acc[r8][0], acc[r8][1], acc[r8][2], acc[r8][3]);
        }
    }
}

// ---------------------------------------------------------------------------
// Warp per node: out[n] = b + dis[n] * sum_e dis[col_e] * y[col_e]
__global__ void __launch_bounds__(256) k_gather(float* __restrict__ out,
                                                const float* __restrict__ b) {
    int gtid = blockIdx.x * blockDim.x + threadIdx.x;
    int n = gtid >> 5;
    int lane = gtid & 31;
    if (n >= N_NODES) return;

    const float4 bias = __ldg(((const float4*)b) + lane);
    float ax = 0.f, ay = 0.f, az = 0.f, aw = 0.f;

    const int start = g_off[n];
    const int end = g_off[n + 1];
    const float dn = g_dis[n];

    for (int e = start; e < end; e++) {
        int c = g_ecol[e];
        float norm = dn * g_dis[c];
        float4 v = __ldg(((const float4*)(g_y + (size_t)c * C)) + lane);
        ax += norm * v.x;
        ay += norm * v.y;
        az += norm * v.z;
        aw += norm * v.w;
    }

    ((float4*)(out + (size_t)n * C))[lane] =
        make_float4(bias.x + ax, bias.y + ay, bias.z + az, bias.w + aw);
}

// ---------------------------------------------------------------------------
extern "C" void kernel_launch(void* const* d_in, const int* in_sizes, int n_in,
                              void* d_out, int out_size) {
    const float* x = (const float*)d_in[0];
    const void*  ei = d_in[1];
    const float* W = (const float*)d_in[2];
    const float* b = (const float*)d_in[3];
    float* out = (float*)d_out;

    k_detect<<<1, 256>>>((const long long*)ei);
    k_norm_edges<<<(N_EDGES + 255) / 256, 256>>>(ei);

    k_zero<<<(N_NODES + 255) / 256, 256>>>();
    k_count_deg<<<(N_EDGES + 255) / 256, 256>>>();
    k_finalize_dis<<<(N_NODES + 255) / 256, 256>>>();
    k_scan<<<1, SCAN_T>>>();
    k_fill_csr<<<(N_EDGES + 255) / 256, 256>>>();

    k_transpose_w<<<(C * C + 255) / 256, 256>>>(W);
    k_gemm<<<(N_NODES + GROWS - 1) / GROWS, 128>>>(x);

    const long long total = (long long)N_NODES * 32;
    k_gather<<<(int)((total + 255) / 256), 256>>>(out, b);
}